// round 6
// baseline (speedup 1.0000x reference)
#include <cuda_runtime.h>

#define HID   128
#define NB    16
#define NPTS  10000
#define OUTD  5
#define LTOT  (NB * NPTS)      // 160000 points
#define BP    128              // points per block
#define WROWS 32               // weight rows staged per phase (dup'd)

// Scratch (device globals — no allocation allowed)
__device__ float g_gate[4 * NB * HID];   // gates per layer/batch/feature
__device__ float g_M[NB * HID * 8];      // folded gate3*(Wtf@bc^T), padded 8/[b,g]
__device__ float g_c[NB * 8];            // folded btf·bc

typedef unsigned long long u64;

__device__ __forceinline__ u64 pack2(float lo, float hi) {
    u64 r; asm("mov.b64 %0, {%1, %2};" : "=l"(r) : "f"(lo), "f"(hi)); return r;
}
__device__ __forceinline__ void unpack2(u64 v, float& lo, float& hi) {
    asm("mov.b64 {%0, %1}, %2;" : "=f"(lo), "=f"(hi) : "l"(v));
}
__device__ __forceinline__ void ffma2(u64& d, u64 a, u64 b) {
    asm("fma.rn.f32x2 %0, %1, %2, %0;" : "+l"(d) : "l"(a), "l"(b));
}
__device__ __forceinline__ float rowdy_f(float t, float a, float w) {
    float th; asm("tanh.approx.f32 %0, %1;" : "=f"(th) : "f"(t));
    return th + a * __sinf(w * t);
}

// ---------------------------------------------------------------------------
// Kernel 1: branch MLP, gates, folded final matrices. grid=16, block=512.
// ---------------------------------------------------------------------------
__global__ void __launch_bounds__(512, 1) branch_kernel(
    const float* __restrict__ params, const float* __restrict__ Wb0,
    const float* __restrict__ bb0,    const float* __restrict__ Wb,
    const float* __restrict__ bb,     const float* __restrict__ Wbf,
    const float* __restrict__ bbf,    const float* __restrict__ ab,
    const float* __restrict__ wb,     const float* __restrict__ Wtf,
    const float* __restrict__ btf)
{
    const int b   = blockIdx.x;
    const int tid = threadIdx.x;
    const int j   = tid & 127;
    const int q   = tid >> 7;            // 0..3, k-range split

    __shared__ float sh_h[HID];
    __shared__ float sh_part[4 * HID];
    __shared__ float sh_bc[OUTD][HID];
    __shared__ float sh_p[8];

    if (tid < 6) sh_p[tid] = params[b * 6 + tid];
    __syncthreads();

    float h = 0.f, gate = 0.f;           // live only in q==0
    if (q == 0) {
        float t = bb0[j];
#pragma unroll
        for (int k = 0; k < 6; k++) t += sh_p[k] * Wb0[k * HID + j];
        h = rowdy_f(t, ab[j], wb[j]);
        gate = h;
        sh_h[j] = h;
        g_gate[(0 * NB + b) * HID + j] = gate;
    }
    __syncthreads();

    for (int i = 0; i < 3; i++) {
        const float* W = Wb + i * HID * HID;
        float tp = 0.f;
#pragma unroll 8
        for (int k = q * 32; k < q * 32 + 32; k++) tp += sh_h[k] * W[k * HID + j];
        sh_part[q * HID + j] = tp;
        __syncthreads();
        if (q == 0) {
            float t2 = bb[i * HID + j] + sh_part[j] + sh_part[HID + j]
                     + sh_part[2 * HID + j] + sh_part[3 * HID + j];
            h = rowdy_f(t2, ab[(i + 1) * HID + j], wb[(i + 1) * HID + j]);
            sh_h[j] = h;
            gate += h;
            g_gate[((i + 1) * NB + b) * HID + j] = gate;
        }
        __syncthreads();
    }

    // branch_out -> sh_bc[o][j], k-split
    {
        float tb[OUTD] = {0.f, 0.f, 0.f, 0.f, 0.f};
#pragma unroll 4
        for (int k = q * 32; k < q * 32 + 32; k++) {
            float hv = sh_h[k];
#pragma unroll
            for (int o = 0; o < OUTD; o++)
                tb[o] += hv * Wbf[k * (HID * OUTD) + o * HID + j];
        }
#pragma unroll
        for (int o = 0; o < OUTD; o++) {
            sh_part[q * HID + j] = tb[o];
            __syncthreads();
            if (q == 0)
                sh_bc[o][j] = bbf[o * HID + j] + sh_part[j] + sh_part[HID + j]
                            + sh_part[2 * HID + j] + sh_part[3 * HID + j];
            __syncthreads();
        }
    }

    // M'[b][g][o] = gate3[g] * sum_h Wtf[g][h]*bc[o][h]
    {
        float am[OUTD] = {0.f, 0.f, 0.f, 0.f, 0.f};
#pragma unroll 4
        for (int hh = q * 32; hh < q * 32 + 32; hh++) {
            float w = __ldg(&Wtf[j * HID + hh]);
#pragma unroll
            for (int o = 0; o < OUTD; o++) am[o] += w * sh_bc[o][hh];
        }
#pragma unroll
        for (int o = 0; o < OUTD; o++) {
            sh_part[q * HID + j] = am[o];
            __syncthreads();
            if (q == 0)
                g_M[(b * HID + j) * 8 + o] = gate *
                    (sh_part[j] + sh_part[HID + j] + sh_part[2 * HID + j] + sh_part[3 * HID + j]);
            __syncthreads();
        }
        if (q == 0) { g_M[(b * HID + j) * 8 + 5] = 0.f;
                      g_M[(b * HID + j) * 8 + 6] = 0.f;
                      g_M[(b * HID + j) * 8 + 7] = 0.f; }
    }
    if (tid < OUTD) {
        float c = 0.f;
#pragma unroll 8
        for (int hh = 0; hh < HID; hh++) c += btf[hh] * sh_bc[tid][hh];
        g_c[b * 8 + tid] = c;
    }
    if (tid >= OUTD && tid < 8) g_c[b * 8 + tid] = 0.f;
}

// ---------------------------------------------------------------------------
// Kernel 2: fused trunk. 512 threads, tile 8 pts x 4 feats. FFMA2 pairs over
// POINTS; weights stored DUPLICATED in SMEM (staged with dup at STS time) so
// the inner loop has zero pack MOVs. Smem 96KB -> 2 CTAs/SM.
//
// Xs layout: [k][128 pts], 32B point-chunks XOR-swizzled by (k>>2)&3.
// Ws layout: [32 rows][256 floats dup], pair q=(j>>1) stored at slot
//            (q>>1)+(q&1)*32, 16B per slot -> both B loads conflict-free.
// ---------------------------------------------------------------------------
extern "C" __global__ void __launch_bounds__(512, 2)
trunk_kernel(const float* __restrict__ coords, const float* __restrict__ sdf,
             const float* __restrict__ Wt0,    const float* __restrict__ bt0,
             const float* __restrict__ Wt,     const float* __restrict__ bt,
             const float* __restrict__ at,     const float* __restrict__ wt,
             float* __restrict__ out)
{
    extern __shared__ float smem[];
    float* Xs = smem;                       // [128][128]
    float* Ws = smem + HID * HID;           // [WROWS][256] dup'd weights

    const int tid = threadIdx.x;
    // warp-internal: 4 point-groups x 8 feature-groups
    const int fg  = (tid & 7) | (((tid >> 5) & 3) << 3);   // 0..31 (4 feats each)
    const int pg  = ((tid >> 3) & 3) | ((tid >> 7) << 2);  // 0..15 (8 pts each)
    const int j0  = fg * 4;
    const int p_lo = pg * 8;
    const int fg4 = fg * 4;                 // B float offset
    const int pgx = pg << 3;                // A chunk base (floats)
    const int cswz = (pgx ^ ((fg & 3) << 3));  // store chunk offset (j>>2 == fg)

    const int p0     = blockIdx.x * BP;
    const int bstart = p0 / NPTS;
    const int bound  = (bstart + 1) * NPTS - p0;
    const bool uni   = ((p_lo < bound) == (p_lo + 7 < bound));
    const int  bu    = (p_lo < bound) ? bstart : bstart + 1;

    // prefetch phase 0 (layer 1 rows 0..31) into registers
    float4 wreg0 = __ldg(&((const float4*)Wt)[tid]);
    float4 wreg1 = __ldg(&((const float4*)Wt)[tid + 512]);

    // ---- layer 0: (coords,sdf) 4 -> 128 ----
    {
        float in4[8][4];
#pragma unroll
        for (int pi = 0; pi < 8; pi++) {
            int gp = p0 + p_lo + pi;
            in4[pi][0] = coords[gp * 3 + 0];
            in4[pi][1] = coords[gp * 3 + 1];
            in4[pi][2] = coords[gp * 3 + 2];
            in4[pi][3] = sdf[gp];
        }
#pragma unroll
        for (int i = 0; i < 4; i++) {
            int j = j0 + i;
            float w0 = __ldg(&Wt0[0 * HID + j]);
            float w1 = __ldg(&Wt0[1 * HID + j]);
            float w2 = __ldg(&Wt0[2 * HID + j]);
            float w3 = __ldg(&Wt0[3 * HID + j]);
            float btv = __ldg(&bt0[j]);
            float av  = __ldg(&at[j]);
            float wv  = __ldg(&wt[j]);
            float v[8];
#pragma unroll
            for (int pi = 0; pi < 8; pi++) {
                float s = btv;
                s += in4[pi][0] * w0; s += in4[pi][1] * w1;
                s += in4[pi][2] * w2; s += in4[pi][3] * w3;
                v[pi] = rowdy_f(s, av, wv);
            }
            if (uni) {
                float g = __ldg(&g_gate[(0 * NB + bu) * HID + j]);
#pragma unroll
                for (int pi = 0; pi < 8; pi++) v[pi] *= g;
            } else {
#pragma unroll
                for (int pi = 0; pi < 8; pi++) {
                    int b = (p_lo + pi < bound) ? bstart : bstart + 1;
                    v[pi] *= __ldg(&g_gate[(0 * NB + b) * HID + j]);
                }
            }
            ulonglong2 s0, s1;
            s0.x = pack2(v[0], v[1]); s0.y = pack2(v[2], v[3]);
            s1.x = pack2(v[4], v[5]); s1.y = pack2(v[6], v[7]);
            float* dst = &Xs[j * HID + cswz];
            *(ulonglong2*)dst       = s0;
            *(ulonglong2*)(dst + 4) = s1;
        }
    }
    __syncthreads();

    // ---- layers 1..3, each in 4 phases of 32 k-rows ----
    const int stg_r = tid >> 5;             // staging row (per i offset +16)
    const int stg_c = tid & 31;             // staging float4 col
    for (int l = 1; l < 4; l++) {
        u64 acc[4][4];                      // [feature i][point pair pp]
#pragma unroll
        for (int i = 0; i < 4; i++)
#pragma unroll
            for (int pp = 0; pp < 4; pp++) acc[i][pp] = 0ull;

        for (int h = 0; h < 4; h++) {
            // dup-store prefetched weights: rows stg_r and stg_r+16
            {
                ulonglong2 d0, d1;
                d0.x = pack2(wreg0.x, wreg0.x); d0.y = pack2(wreg0.y, wreg0.y);
                d1.x = pack2(wreg0.z, wreg0.z); d1.y = pack2(wreg0.w, wreg0.w);
                float* w = &Ws[stg_r * 256 + stg_c * 4];
                *(ulonglong2*)w         = d0;
                *(ulonglong2*)(w + 128) = d1;
                d0.x = pack2(wreg1.x, wreg1.x); d0.y = pack2(wreg1.y, wreg1.y);
                d1.x = pack2(wreg1.z, wreg1.z); d1.y = pack2(wreg1.w, wreg1.w);
                w = &Ws[(stg_r + 16) * 256 + stg_c * 4];
                *(ulonglong2*)w         = d0;
                *(ulonglong2*)(w + 128) = d1;
            }
            __syncthreads();                 // Ws visible

            int nxt = (l - 1) * 4 + h + 1;   // next phase 0..11
            if (nxt < 12) {
                const float4* src = (const float4*)(Wt + nxt * (WROWS * HID));
                wreg0 = __ldg(&src[tid]);
                wreg1 = __ldg(&src[tid + 512]);
            }

            const float* XsH = Xs + h * (WROWS * HID);
#pragma unroll
            for (int kk = 0; kk < 32; kk++) {
                const int sw = ((kk >> 2) & 3) << 3;
                const float* ap = &XsH[kk * 128 + (pgx ^ sw)];
                ulonglong2 a01 = *(const ulonglong2*)ap;         // pts 0-3
                ulonglong2 a23 = *(const ulonglong2*)(ap + 4);   // pts 4-7
                ulonglong2 b01 = *(const ulonglong2*)&Ws[kk * 256 + fg4];        // feats j0,j0+1 dup
                ulonglong2 b23 = *(const ulonglong2*)&Ws[kk * 256 + 128 + fg4];  // feats j0+2,j0+3 dup
                ffma2(acc[0][0], a01.x, b01.x); ffma2(acc[0][1], a01.y, b01.x);
                ffma2(acc[0][2], a23.x, b01.x); ffma2(acc[0][3], a23.y, b01.x);
                ffma2(acc[1][0], a01.x, b01.y); ffma2(acc[1][1], a01.y, b01.y);
                ffma2(acc[1][2], a23.x, b01.y); ffma2(acc[1][3], a23.y, b01.y);
                ffma2(acc[2][0], a01.x, b23.x); ffma2(acc[2][1], a01.y, b23.x);
                ffma2(acc[2][2], a23.x, b23.x); ffma2(acc[2][3], a23.y, b23.x);
                ffma2(acc[3][0], a01.x, b23.y); ffma2(acc[3][1], a01.y, b23.y);
                ffma2(acc[3][2], a23.x, b23.y); ffma2(acc[3][3], a23.y, b23.y);
            }
            __syncthreads();                 // Ws reads done (and Xs after h==3)
        }

        // epilogue: rowdy (+ gate for l<3; gate3 folded into M'), pair stores
        const float* bvec = bt + (l - 1) * HID;
#pragma unroll
        for (int i = 0; i < 4; i++) {
            int j = j0 + i;
            float btv = __ldg(&bvec[j]);
            float av  = __ldg(&at[l * HID + j]);
            float wv  = __ldg(&wt[l * HID + j]);
            float v[8];
#pragma unroll
            for (int pp = 0; pp < 4; pp++) {
                float lo, hi;
                unpack2(acc[i][pp], lo, hi);
                v[2 * pp]     = rowdy_f(lo + btv, av, wv);
                v[2 * pp + 1] = rowdy_f(hi + btv, av, wv);
            }
            if (l < 3) {
                if (uni) {
                    float g = __ldg(&g_gate[(l * NB + bu) * HID + j]);
#pragma unroll
                    for (int pi = 0; pi < 8; pi++) v[pi] *= g;
                } else {
#pragma unroll
                    for (int pi = 0; pi < 8; pi++) {
                        int b = (p_lo + pi < bound) ? bstart : bstart + 1;
                        v[pi] *= __ldg(&g_gate[(l * NB + b) * HID + j]);
                    }
                }
            }
            ulonglong2 s0, s1;
            s0.x = pack2(v[0], v[1]); s0.y = pack2(v[2], v[3]);
            s1.x = pack2(v[4], v[5]); s1.y = pack2(v[6], v[7]);
            float* dst = &Xs[j * HID + cswz];
            *(ulonglong2*)dst       = s0;
            *(ulonglong2*)(dst + 4) = s1;
        }
        __syncthreads();
    }

    // ---- folded final: out[p][o] = c[b][o] + sum_g Xs[g][p] * M'[b][g][o] ----
    {
        float* part = Ws;                     // reuse: [5][4][128] = 2560 floats
        const int p = tid & 127;
        const int q = tid >> 7;               // 0..3, each sums 32 g's
        const int b = (p < bound) ? bstart : bstart + 1;
        const int pc = (p >> 3) << 3;         // point chunk base (floats)
        const int pi = p & 7;
        float o0 = 0.f, o1 = 0.f, o2 = 0.f, o3 = 0.f, o4 = 0.f;
        const float4* Mb = (const float4*)&g_M[b * HID * 8];
#pragma unroll 8
        for (int g = q * 32; g < q * 32 + 32; g++) {
            int sw = ((g >> 2) & 3) << 3;
            float v   = Xs[g * 128 + (pc ^ sw) + pi];
            float4 m0 = __ldg(&Mb[g * 2 + 0]);
            float4 m1 = __ldg(&Mb[g * 2 + 1]);
            o0 += v * m0.x; o1 += v * m0.y; o2 += v * m0.z; o3 += v * m0.w;
            o4 += v * m1.x;
        }
        part[(0 * 4 + q) * 128 + p] = o0;
        part[(1 * 4 + q) * 128 + p] = o1;
        part[(2 * 4 + q) * 128 + p] = o2;
        part[(3 * 4 + q) * 128 + p] = o3;
        part[(4 * 4 + q) * 128 + p] = o4;
        __syncthreads();
        if (tid < BP) {
            const int pp2 = tid;
            const int gp2 = p0 + pp2;
            const int b2  = (pp2 < bound) ? bstart : bstart + 1;
            float* op = out + (size_t)gp2 * OUTD;
#pragma unroll
            for (int o = 0; o < OUTD; o++)
                op[o] = g_c[b2 * 8 + o]
                      + part[(o * 4 + 0) * 128 + pp2]
                      + part[(o * 4 + 1) * 128 + pp2]
                      + part[(o * 4 + 2) * 128 + pp2]
                      + part[(o * 4 + 3) * 128 + pp2];
        }
    }
}

// ---------------------------------------------------------------------------
extern "C" void kernel_launch(void* const* d_in, const int* in_sizes, int n_in,
                              void* d_out, int out_size)
{
    const float* coords = (const float*)d_in[0];
    const float* sdf    = (const float*)d_in[1];
    const float* params = (const float*)d_in[2];
    const float* Wb0    = (const float*)d_in[3];
    const float* bb0    = (const float*)d_in[4];
    const float* Wb     = (const float*)d_in[5];
    const float* bb     = (const float*)d_in[6];
    const float* Wbf    = (const float*)d_in[7];
    const float* bbf    = (const float*)d_in[8];
    const float* ab     = (const float*)d_in[9];
    const float* wb     = (const float*)d_in[10];
    const float* Wt0    = (const float*)d_in[11];
    const float* bt0    = (const float*)d_in[12];
    const float* Wt     = (const float*)d_in[13];
    const float* bt     = (const float*)d_in[14];
    const float* Wtf    = (const float*)d_in[15];
    const float* btf    = (const float*)d_in[16];
    const float* at     = (const float*)d_in[17];
    const float* wt     = (const float*)d_in[18];
    float* out = (float*)d_out;

    static int smem_set = 0;
    const int smem_bytes = (HID * HID + WROWS * 256) * sizeof(float);  // 98304
    if (!smem_set) {
        cudaFuncSetAttribute(trunk_kernel,
                             cudaFuncAttributeMaxDynamicSharedMemorySize,
                             smem_bytes);
        smem_set = 1;
    }

    branch_kernel<<<NB, 512>>>(params, Wb0, bb0, Wb, bb, Wbf, bbf, ab, wb,
                               Wtf, btf);
    trunk_kernel<<<LTOT / BP, 512, smem_bytes>>>(coords, sdf, Wt0, bt0,
                                                 Wt, bt, at, wt, out);
}

// round 8
// speedup vs baseline: 2.4170x; 2.4170x over previous
#include <cuda_runtime.h>
#include <cuda_bf16.h>
#include <cstdint>

#define HID   128
#define NB    16
#define NPTS  10000
#define OUTD  5
#define LTOT  160000
#define BP    128

// ---------------- device scratch (no allocation allowed) -------------------
__device__ float g_gate[4 * NB * HID];
__device__ float g_M[NB * HID * 8];      // gate3-folded Wtf@bc^T, padded 8
__device__ float g_c[NB * 8];
// Pre-transposed, split, pre-swizzled weights: [l][half][plane][n=128][k=64] bf16
__device__ __align__(16) __nv_bfloat16 g_WT[6 * 16384];

// SMEM byte map (per CTA, dynamic):
//  [0,32768)      XH plane  [128 p][128 k] bf16, row 256B, swz ((p&7)<<4)
//  [32768,65536)  XL plane
//  [65536,98304)  W stage: [plane][128 n][64 k] bf16, row 128B, swz ((n&7)<<4)
//  [98304,106496) params (2048 floats)
#define SM_XH 0
#define SM_XL 32768
#define SM_W  65536
#define SM_PAR 98304
#define SM_TOTAL 106496
#define PAR_BT0 0
#define PAR_W0  128
#define PAR_AT  640
#define PAR_WT  1152
#define PAR_BT  1664

__device__ __forceinline__ float rowdy_f(float t, float a, float w) {
    float th; asm("tanh.approx.f32 %0, %1;" : "=f"(th) : "f"(t));
    return th + a * __sinf(w * t);
}
__device__ __forceinline__ void cp_async16(uint32_t smem_dst, const void* gmem_src) {
    asm volatile("cp.async.cg.shared.global [%0], [%1], 16;" :: "r"(smem_dst), "l"(gmem_src));
}
__device__ __forceinline__ void ldsm4(uint32_t* r, uint32_t a) {
    asm volatile("ldmatrix.sync.aligned.m8n8.x4.shared.b16 {%0,%1,%2,%3}, [%4];"
                 : "=r"(r[0]), "=r"(r[1]), "=r"(r[2]), "=r"(r[3]) : "r"(a));
}
__device__ __forceinline__ void mma16816(float* d, const uint32_t* a,
                                         uint32_t b0, uint32_t b1) {
    asm volatile(
        "mma.sync.aligned.m16n8k16.row.col.f32.bf16.bf16.f32 "
        "{%0,%1,%2,%3}, {%4,%5,%6,%7}, {%8,%9}, {%0,%1,%2,%3};"
        : "+f"(d[0]), "+f"(d[1]), "+f"(d[2]), "+f"(d[3])
        : "r"(a[0]), "r"(a[1]), "r"(a[2]), "r"(a[3]), "r"(b0), "r"(b1));
}
// truncation split of (x0,x1) into bf16 hi/lo packed words; store to X planes
__device__ __forceinline__ void store_pair(uint32_t su, int p, int j,
                                           float x0, float x1) {
    uint32_t hi;
    asm("prmt.b32 %0, %1, %2, 0x7632;"
        : "=r"(hi) : "r"(__float_as_uint(x0)), "r"(__float_as_uint(x1)));
    float r0 = x0 - __uint_as_float(__float_as_uint(x0) & 0xFFFF0000u);
    float r1 = x1 - __uint_as_float(__float_as_uint(x1) & 0xFFFF0000u);
    uint32_t lo;
    asm("cvt.rn.bf16x2.f32 %0, %1, %2;" : "=r"(lo) : "f"(r1), "f"(r0));
    uint32_t off = (uint32_t)(p * 256) + (uint32_t)((j * 2) ^ ((p & 7) << 4));
    asm volatile("st.shared.b32 [%0], %1;" :: "r"(su + SM_XH + off), "r"(hi));
    asm volatile("st.shared.b32 [%0], %1;" :: "r"(su + SM_XL + off), "r"(lo));
}

// ---------------------------------------------------------------------------
// Prep: W^T + truncation split + SMEM-image swizzle into g_WT.
// ---------------------------------------------------------------------------
__global__ void prep_kernel(const float* __restrict__ Wt) {
    int idx = blockIdx.x * blockDim.x + threadIdx.x;
    if (idx >= 6 * 16384) return;
    int k     = idx & 63;
    int n     = (idx >> 6) & 127;
    int plane = (idx >> 13) & 1;
    int lh    = idx >> 14;                 // l*2 + h
    int l = lh >> 1, h = lh & 1;
    float w = Wt[l * 16384 + (h * 64 + k) * 128 + n];
    uint32_t wb = __float_as_uint(w);
    __nv_bfloat16 val;
    if (plane == 0) {
        val = __ushort_as_bfloat16((unsigned short)(wb >> 16));
    } else {
        float r = w - __uint_as_float(wb & 0xFFFF0000u);
        val = __float2bfloat16_rn(r);
    }
    int dst = lh * 16384 + plane * 8192 + n * 64 + (k ^ ((n & 7) << 3));
    g_WT[dst] = val;
}

// ---------------------------------------------------------------------------
// Branch MLP + gates + folded final matrices (validated in R5/R6).
// ---------------------------------------------------------------------------
__global__ void __launch_bounds__(512, 1) branch_kernel(
    const float* __restrict__ params, const float* __restrict__ Wb0,
    const float* __restrict__ bb0,    const float* __restrict__ Wb,
    const float* __restrict__ bb,     const float* __restrict__ Wbf,
    const float* __restrict__ bbf,    const float* __restrict__ ab,
    const float* __restrict__ wb,     const float* __restrict__ Wtf,
    const float* __restrict__ btf)
{
    const int b   = blockIdx.x;
    const int tid = threadIdx.x;
    const int j   = tid & 127;
    const int q   = tid >> 7;

    __shared__ float sh_h[HID];
    __shared__ float sh_part[4 * HID];
    __shared__ float sh_bc[OUTD][HID];
    __shared__ float sh_p[8];

    if (tid < 6) sh_p[tid] = params[b * 6 + tid];
    __syncthreads();

    float h = 0.f, gate = 0.f;
    if (q == 0) {
        float t = bb0[j];
#pragma unroll
        for (int k = 0; k < 6; k++) t += sh_p[k] * Wb0[k * HID + j];
        h = tanhf(t) + ab[j] * __sinf(wb[j] * t);
        gate = h;
        sh_h[j] = h;
        g_gate[(0 * NB + b) * HID + j] = gate;
    }
    __syncthreads();

    for (int i = 0; i < 3; i++) {
        const float* W = Wb + i * HID * HID;
        float tp = 0.f;
#pragma unroll 8
        for (int k = q * 32; k < q * 32 + 32; k++) tp += sh_h[k] * W[k * HID + j];
        sh_part[q * HID + j] = tp;
        __syncthreads();
        if (q == 0) {
            float t2 = bb[i * HID + j] + sh_part[j] + sh_part[HID + j]
                     + sh_part[2 * HID + j] + sh_part[3 * HID + j];
            h = tanhf(t2) + ab[(i + 1) * HID + j] * __sinf(wb[(i + 1) * HID + j] * t2);
            sh_h[j] = h;
            gate += h;
            g_gate[((i + 1) * NB + b) * HID + j] = gate;
        }
        __syncthreads();
    }

    {
        float tb[OUTD] = {0.f, 0.f, 0.f, 0.f, 0.f};
#pragma unroll 4
        for (int k = q * 32; k < q * 32 + 32; k++) {
            float hv = sh_h[k];
#pragma unroll
            for (int o = 0; o < OUTD; o++)
                tb[o] += hv * Wbf[k * (HID * OUTD) + o * HID + j];
        }
#pragma unroll
        for (int o = 0; o < OUTD; o++) {
            sh_part[q * HID + j] = tb[o];
            __syncthreads();
            if (q == 0)
                sh_bc[o][j] = bbf[o * HID + j] + sh_part[j] + sh_part[HID + j]
                            + sh_part[2 * HID + j] + sh_part[3 * HID + j];
            __syncthreads();
        }
    }

    {
        float am[OUTD] = {0.f, 0.f, 0.f, 0.f, 0.f};
#pragma unroll 4
        for (int hh = q * 32; hh < q * 32 + 32; hh++) {
            float w = __ldg(&Wtf[j * HID + hh]);
#pragma unroll
            for (int o = 0; o < OUTD; o++) am[o] += w * sh_bc[o][hh];
        }
#pragma unroll
        for (int o = 0; o < OUTD; o++) {
            sh_part[q * HID + j] = am[o];
            __syncthreads();
            if (q == 0)
                g_M[(b * HID + j) * 8 + o] = gate *
                    (sh_part[j] + sh_part[HID + j] + sh_part[2 * HID + j] + sh_part[3 * HID + j]);
            __syncthreads();
        }
        if (q == 0) { g_M[(b * HID + j) * 8 + 5] = 0.f;
                      g_M[(b * HID + j) * 8 + 6] = 0.f;
                      g_M[(b * HID + j) * 8 + 7] = 0.f; }
    }
    if (tid < OUTD) {
        float c = 0.f;
#pragma unroll 8
        for (int hh = 0; hh < HID; hh++) c += btf[hh] * sh_bc[tid][hh];
        g_c[b * 8 + tid] = c;
    }
    if (tid >= OUTD && tid < 8) g_c[b * 8 + tid] = 0.f;
}

// ---------------------------------------------------------------------------
// Trunk: HMMA bf16-split. 256 threads, 8 warps (4 M x 2 N), warp tile 32x64.
// ---------------------------------------------------------------------------
__global__ void __launch_bounds__(256, 2)
trunk_kernel(const float* __restrict__ coords, const float* __restrict__ sdf,
             const float* __restrict__ Wt0,    const float* __restrict__ bt0,
             const float* __restrict__ bt,     const float* __restrict__ at,
             const float* __restrict__ wt,     float* __restrict__ out)
{
    extern __shared__ char smem[];
    float* sp  = (float*)(smem + SM_PAR);
    float* scr = (float*)smem;                  // fp32 scratch aliases X planes
    const uint32_t su = (uint32_t)__cvta_generic_to_shared(smem);

    const int tid  = threadIdx.x;
    const int lane = tid & 31;
    const int wid  = tid >> 5;
    const int wm   = wid & 3;                   // M tile 0..3
    const int wn   = wid >> 2;                  // N half 0..1
    const int la7  = lane & 7;
    const int lb3  = (lane >> 3) & 1;
    const int lb4  = lane >> 4;
    const int gid  = lane >> 2;
    const int tig  = lane & 3;
    const uint32_t swz = (uint32_t)la7 << 4;

    const int p0     = blockIdx.x * BP;
    const int bstart = p0 / NPTS;
    const int bound  = (bstart + 1) * NPTS - p0;
    const int b1     = (bstart + 1 < NB) ? bstart + 1 : NB - 1;

    // stage layer-1 half0 immediately
    {
        const char* src = (const char*)g_WT;
#pragma unroll
        for (int i = 0; i < 8; i++)
            cp_async16(su + SM_W + (tid + i * 256) * 16, src + (tid + i * 256) * 16);
        asm volatile("cp.async.commit_group;");
    }

    // stage params
    if (tid < 128) sp[PAR_BT0 + tid] = bt0[tid];
    for (int i = tid; i < 512; i += 256) {
        sp[PAR_W0 + i] = Wt0[i];
        sp[PAR_AT + i] = at[i];
        sp[PAR_WT + i] = wt[i];
    }
    for (int i = tid; i < 384; i += 256) sp[PAR_BT + i] = bt[i];
    __syncthreads();

    // ---- layer 0: 2 threads per point, 64 features each ----
    {
        const int p  = tid & 127;
        const int jh = tid >> 7;
        const int gp = p0 + p;
        float c0 = coords[gp * 3 + 0];
        float c1 = coords[gp * 3 + 1];
        float c2 = coords[gp * 3 + 2];
        float c3 = sdf[gp];
        const int bpt = (p < bound) ? bstart : b1;
        const float* gv = &g_gate[(0 * NB + bpt) * HID];
#pragma unroll 4
        for (int i = 0; i < 32; i++) {
            int j = jh * 64 + 2 * i;
            float t0 = sp[PAR_BT0 + j]
                     + c0 * sp[PAR_W0 + j]       + c1 * sp[PAR_W0 + 128 + j]
                     + c2 * sp[PAR_W0 + 256 + j] + c3 * sp[PAR_W0 + 384 + j];
            float t1 = sp[PAR_BT0 + j + 1]
                     + c0 * sp[PAR_W0 + j + 1]       + c1 * sp[PAR_W0 + 128 + j + 1]
                     + c2 * sp[PAR_W0 + 256 + j + 1] + c3 * sp[PAR_W0 + 384 + j + 1];
            float x0 = rowdy_f(t0, sp[PAR_AT + j], sp[PAR_WT + j]) * __ldg(&gv[j]);
            float x1 = rowdy_f(t1, sp[PAR_AT + j + 1], sp[PAR_WT + j + 1]) * __ldg(&gv[j + 1]);
            store_pair(su, p, j, x0, x1);
        }
    }

    float acc[2][8][4];

    // ---- layers 1..3 ----
    for (int l = 1; l <= 3; l++) {
        asm volatile("cp.async.wait_group 0;");
        __syncthreads();       // W half0 + X plane writes visible

#pragma unroll
        for (int s = 0; s < 2; s++)
#pragma unroll
            for (int t = 0; t < 8; t++)
#pragma unroll
                for (int i = 0; i < 4; i++) acc[s][t][i] = 0.f;

        for (int half = 0; half < 2; half++) {
#pragma unroll
            for (int kl = 0; kl < 4; kl++) {
                const int ks = half * 4 + kl;
                uint32_t ah[2][4], al[2][4];
#pragma unroll
                for (int s = 0; s < 2; s++) {
                    uint32_t arow = (uint32_t)(wm * 32 + s * 16 + la7 + 8 * lb3);
                    uint32_t aoff = ((uint32_t)(ks * 32 + 16 * lb4)) ^ swz;
                    ldsm4(ah[s], su + SM_XH + arow * 256 + aoff);
                    ldsm4(al[s], su + SM_XL + arow * 256 + aoff);
                }
#pragma unroll
                for (int q = 0; q < 4; q++) {
                    uint32_t bh[4], bl[4];
                    uint32_t nrow = (uint32_t)(wn * 64 + q * 16 + la7 + 8 * lb4);
                    uint32_t boff = ((uint32_t)(kl * 32 + 16 * lb3)) ^ swz;
                    ldsm4(bh, su + SM_W + nrow * 128 + boff);
                    ldsm4(bl, su + SM_W + 16384 + nrow * 128 + boff);
#pragma unroll
                    for (int s = 0; s < 2; s++) {
#pragma unroll
                        for (int u = 0; u < 2; u++) {
                            float* d = acc[s][q * 2 + u];
                            mma16816(d, ah[s], bh[2 * u], bh[2 * u + 1]);
                            mma16816(d, al[s], bh[2 * u], bh[2 * u + 1]);
                            mma16816(d, ah[s], bl[2 * u], bl[2 * u + 1]);
                        }
                    }
                }
            }
            __syncthreads();                 // this half's W reads done
            if (half == 0) {                 // stage half1
                const char* src = (const char*)(g_WT + ((l - 1) * 2 + 1) * 16384);
#pragma unroll
                for (int i = 0; i < 8; i++)
                    cp_async16(su + SM_W + (tid + i * 256) * 16, src + (tid + i * 256) * 16);
                asm volatile("cp.async.commit_group;");
                asm volatile("cp.async.wait_group 0;");
                __syncthreads();
            }
        }

        if (l < 3) {                         // overlap next-layer stage with epilogue
            const char* src = (const char*)(g_WT + (l * 2) * 16384);
#pragma unroll
            for (int i = 0; i < 8; i++)
                cp_async16(su + SM_W + (tid + i * 256) * 16, src + (tid + i * 256) * 16);
            asm volatile("cp.async.commit_group;");
        }

        // epilogue
        const float* bvec = &sp[PAR_BT + (l - 1) * 128];
        const float* avec = &sp[PAR_AT + l * 128];
        const float* wvec = &sp[PAR_WT + l * 128];
#pragma unroll
        for (int s = 0; s < 2; s++) {
            const int pA = wm * 32 + s * 16 + gid;
            const int bA = (pA < bound) ? bstart : b1;
            const int bB = (pA + 8 < bound) ? bstart : b1;
#pragma unroll
            for (int t = 0; t < 8; t++) {
                const int jA = wn * 64 + t * 8 + 2 * tig;
                float* d = acc[s][t];
                float x0 = rowdy_f(d[0] + bvec[jA],     avec[jA],     wvec[jA]);
                float x1 = rowdy_f(d[1] + bvec[jA + 1], avec[jA + 1], wvec[jA + 1]);
                float x2 = rowdy_f(d[2] + bvec[jA],     avec[jA],     wvec[jA]);
                float x3 = rowdy_f(d[3] + bvec[jA + 1], avec[jA + 1], wvec[jA + 1]);
                if (l < 3) {
                    const float* gA = &g_gate[(l * NB + bA) * HID];
                    const float* gB = &g_gate[(l * NB + bB) * HID];
                    x0 *= __ldg(&gA[jA]); x1 *= __ldg(&gA[jA + 1]);
                    x2 *= __ldg(&gB[jA]); x3 *= __ldg(&gB[jA + 1]);
                    store_pair(su, pA,     jA, x0, x1);
                    store_pair(su, pA + 8, jA, x2, x3);
                } else {
                    scr[jA * 128 + pA]           = x0;
                    scr[(jA + 1) * 128 + pA]     = x1;
                    scr[jA * 128 + pA + 8]       = x2;
                    scr[(jA + 1) * 128 + pA + 8] = x3;
                }
            }
        }
        __syncthreads();
    }

    // ---- folded final: out[p][o] = c[b][o] + sum_g x[p][g] * M'[b][g][o] ----
    {
        float* part = (float*)(smem + SM_W);       // [5][2][128]
        const int p = tid & 127;
        const int q = tid >> 7;                    // 0..1, 64 g's each
        const int b = (p < bound) ? bstart : b1;
        float o0 = 0.f, o1 = 0.f, o2 = 0.f, o3 = 0.f, o4 = 0.f;
        const float4* Mb = (const float4*)&g_M[b * HID * 8];
#pragma unroll 8
        for (int g = q * 64; g < q * 64 + 64; g++) {
            float v   = scr[g * 128 + p];
            float4 m0 = __ldg(&Mb[g * 2 + 0]);
            float4 m1 = __ldg(&Mb[g * 2 + 1]);
            o0 += v * m0.x; o1 += v * m0.y; o2 += v * m0.z; o3 += v * m0.w;
            o4 += v * m1.x;
        }
        part[(0 * 2 + q) * 128 + p] = o0;
        part[(1 * 2 + q) * 128 + p] = o1;
        part[(2 * 2 + q) * 128 + p] = o2;
        part[(3 * 2 + q) * 128 + p] = o3;
        part[(4 * 2 + q) * 128 + p] = o4;
        __syncthreads();
        if (tid < BP) {
            const int gp = p0 + tid;
            const int b2 = (tid < bound) ? bstart : b1;
            float* op = out + (size_t)gp * OUTD;
#pragma unroll
            for (int o = 0; o < OUTD; o++)
                op[o] = g_c[b2 * 8 + o]
                      + part[(o * 2 + 0) * 128 + tid]
                      + part[(o * 2 + 1) * 128 + tid];
        }
    }
}

// ---------------------------------------------------------------------------
extern "C" void kernel_launch(void* const* d_in, const int* in_sizes, int n_in,
                              void* d_out, int out_size)
{
    const float* coords = (const float*)d_in[0];
    const float* sdf    = (const float*)d_in[1];
    const float* params = (const float*)d_in[2];
    const float* Wb0    = (const float*)d_in[3];
    const float* bb0    = (const float*)d_in[4];
    const float* Wb     = (const float*)d_in[5];
    const float* bb     = (const float*)d_in[6];
    const float* Wbf    = (const float*)d_in[7];
    const float* bbf    = (const float*)d_in[8];
    const float* ab     = (const float*)d_in[9];
    const float* wb     = (const float*)d_in[10];
    const float* Wt0    = (const float*)d_in[11];
    const float* bt0    = (const float*)d_in[12];
    const float* Wt     = (const float*)d_in[13];
    const float* bt     = (const float*)d_in[14];
    const float* Wtf    = (const float*)d_in[15];
    const float* btf    = (const float*)d_in[16];
    const float* at     = (const float*)d_in[17];
    const float* wt     = (const float*)d_in[18];
    float* out = (float*)d_out;

    static int smem_set = 0;
    if (!smem_set) {
        cudaFuncSetAttribute(trunk_kernel,
                             cudaFuncAttributeMaxDynamicSharedMemorySize,
                             SM_TOTAL);
        smem_set = 1;
    }

    prep_kernel<<<384, 256>>>(Wt);
    branch_kernel<<<NB, 512>>>(params, Wb0, bb0, Wb, bb, Wbf, bbf, ab, wb,
                               Wtf, btf);
    trunk_kernel<<<LTOT / BP, 256, SM_TOTAL>>>(coords, sdf, Wt0, bt0,
                                               bt, at, wt, out);
}

// round 9
// speedup vs baseline: 2.8639x; 1.1849x over previous
#include <cuda_runtime.h>
#include <cuda_fp16.h>
#include <cstdint>

#define HID   128
#define NB    16
#define NPTS  10000
#define OUTD  5
#define LTOT  160000
#define BP    128

// ---------------- device scratch (no allocation allowed) -------------------
__device__ float g_gate[4 * NB * HID];
__device__ float g_M[NB * HID * 8];      // gate3-folded Wtf@bc^T, padded 8
__device__ float g_c[NB * 8];
// Pre-transposed fp16-split pre-swizzled weights:
// [l][half][plane: wh/wl][n=128][k=64] fp16
__device__ __align__(16) __half g_WT[6 * 16384];

// SMEM byte map (per CTA, dynamic):
//  [0,32768)      X plane [128 p][128 k] fp16, row 256B, swz ((p&7)<<4)
//  [32768,65536)  W stage: [plane][128 n][64 k] fp16, row 128B, swz ((n&7)<<4)
//  [65536,73728)  params (2048 floats)
//  [73728,78848)  final-contraction partials (1280 floats)
#define SM_X   0
#define SM_W   32768
#define SM_PAR 65536
#define SM_PART 73728
#define SM_TOTAL 78848
#define PAR_BT0 0
#define PAR_W0  128
#define PAR_AT  640
#define PAR_WT  1152
#define PAR_BT  1664

__device__ __forceinline__ float rowdy_f(float t, float a, float w) {
    float th; asm("tanh.approx.f32 %0, %1;" : "=f"(th) : "f"(t));
    return th + a * __sinf(w * t);
}
__device__ __forceinline__ void cp_async16(uint32_t smem_dst, const void* gmem_src) {
    asm volatile("cp.async.cg.shared.global [%0], [%1], 16;" :: "r"(smem_dst), "l"(gmem_src));
}
__device__ __forceinline__ void ldsm4(uint32_t* r, uint32_t a) {
    asm volatile("ldmatrix.sync.aligned.m8n8.x4.shared.b16 {%0,%1,%2,%3}, [%4];"
                 : "=r"(r[0]), "=r"(r[1]), "=r"(r[2]), "=r"(r[3]) : "r"(a));
}
__device__ __forceinline__ void mma16816(float* d, const uint32_t* a,
                                         uint32_t b0, uint32_t b1) {
    asm volatile(
        "mma.sync.aligned.m16n8k16.row.col.f32.f16.f16.f32 "
        "{%0,%1,%2,%3}, {%4,%5,%6,%7}, {%8,%9}, {%0,%1,%2,%3};"
        : "+f"(d[0]), "+f"(d[1]), "+f"(d[2]), "+f"(d[3])
        : "r"(a[0]), "r"(a[1]), "r"(a[2]), "r"(a[3]), "r"(b0), "r"(b1));
}
// pack (x0,x1) to fp16x2 and store to X plane (single instr pack + 1 STS)
__device__ __forceinline__ void store_x(uint32_t su, int p, int j,
                                        float x0, float x1) {
    uint32_t hx;
    asm("cvt.rn.f16x2.f32 %0, %1, %2;" : "=r"(hx) : "f"(x1), "f"(x0));
    uint32_t off = (uint32_t)(p * 256) + (uint32_t)((j * 2) ^ ((p & 7) << 4));
    asm volatile("st.shared.b32 [%0], %1;" :: "r"(su + SM_X + off), "r"(hx));
}

// ---------------------------------------------------------------------------
// Branch MLP + gates + folded matrices (blocks 0..15) and weight prep
// (blocks 16..111): W^T + fp16 split + SMEM-image swizzle into g_WT.
// ---------------------------------------------------------------------------
__global__ void __launch_bounds__(512, 1) branch_prep_kernel(
    const float* __restrict__ params, const float* __restrict__ Wb0,
    const float* __restrict__ bb0,    const float* __restrict__ Wb,
    const float* __restrict__ bb,     const float* __restrict__ Wbf,
    const float* __restrict__ bbf,    const float* __restrict__ ab,
    const float* __restrict__ wb,     const float* __restrict__ Wtf,
    const float* __restrict__ btf,    const float* __restrict__ Wt)
{
    const int tid = threadIdx.x;

    if (blockIdx.x >= NB) {
        // ---- prep: 96 blocks x 512 thr x 2 elems = 98304 ----
        int base = (blockIdx.x - NB) * 512 + tid;
#pragma unroll
        for (int r = 0; r < 2; r++) {
            int idx = base + r * 49152;
            int k     = idx & 63;
            int n     = (idx >> 6) & 127;
            int plane = (idx >> 13) & 1;
            int lh    = idx >> 14;            // l*2 + h
            int l = lh >> 1, h = lh & 1;
            float w = Wt[l * 16384 + (h * 64 + k) * 128 + n];
            __half wh = __float2half_rn(w);
            __half val;
            if (plane == 0) val = wh;
            else            val = __float2half_rn(w - __half2float(wh));
            g_WT[lh * 16384 + plane * 8192 + n * 64 + (k ^ ((n & 7) << 3))] = val;
        }
        return;
    }

    const int b = blockIdx.x;
    const int j = tid & 127;
    const int q = tid >> 7;

    __shared__ float sh_h[HID];
    __shared__ float sh_part[4 * HID];
    __shared__ float sh_bc[OUTD][HID];
    __shared__ float sh_p[8];

    if (tid < 6) sh_p[tid] = params[b * 6 + tid];
    __syncthreads();

    float h = 0.f, gate = 0.f;
    if (q == 0) {
        float t = bb0[j];
#pragma unroll
        for (int k = 0; k < 6; k++) t += sh_p[k] * Wb0[k * HID + j];
        h = tanhf(t) + ab[j] * __sinf(wb[j] * t);
        gate = h;
        sh_h[j] = h;
        g_gate[(0 * NB + b) * HID + j] = gate;
    }
    __syncthreads();

    for (int i = 0; i < 3; i++) {
        const float* W = Wb + i * HID * HID;
        float tp = 0.f;
#pragma unroll 8
        for (int k = q * 32; k < q * 32 + 32; k++) tp += sh_h[k] * W[k * HID + j];
        sh_part[q * HID + j] = tp;
        __syncthreads();
        if (q == 0) {
            float t2 = bb[i * HID + j] + sh_part[j] + sh_part[HID + j]
                     + sh_part[2 * HID + j] + sh_part[3 * HID + j];
            h = tanhf(t2) + ab[(i + 1) * HID + j] * __sinf(wb[(i + 1) * HID + j] * t2);
            sh_h[j] = h;
            gate += h;
            g_gate[((i + 1) * NB + b) * HID + j] = gate;
        }
        __syncthreads();
    }

    {
        float tb[OUTD] = {0.f, 0.f, 0.f, 0.f, 0.f};
#pragma unroll 4
        for (int k = q * 32; k < q * 32 + 32; k++) {
            float hv = sh_h[k];
#pragma unroll
            for (int o = 0; o < OUTD; o++)
                tb[o] += hv * Wbf[k * (HID * OUTD) + o * HID + j];
        }
#pragma unroll
        for (int o = 0; o < OUTD; o++) {
            sh_part[q * HID + j] = tb[o];
            __syncthreads();
            if (q == 0)
                sh_bc[o][j] = bbf[o * HID + j] + sh_part[j] + sh_part[HID + j]
                            + sh_part[2 * HID + j] + sh_part[3 * HID + j];
            __syncthreads();
        }
    }

    {
        float am[OUTD] = {0.f, 0.f, 0.f, 0.f, 0.f};
#pragma unroll 4
        for (int hh = q * 32; hh < q * 32 + 32; hh++) {
            float w = __ldg(&Wtf[j * HID + hh]);
#pragma unroll
            for (int o = 0; o < OUTD; o++) am[o] += w * sh_bc[o][hh];
        }
#pragma unroll
        for (int o = 0; o < OUTD; o++) {
            sh_part[q * HID + j] = am[o];
            __syncthreads();
            if (q == 0)
                g_M[(b * HID + j) * 8 + o] = gate *
                    (sh_part[j] + sh_part[HID + j] + sh_part[2 * HID + j] + sh_part[3 * HID + j]);
            __syncthreads();
        }
        if (q == 0) { g_M[(b * HID + j) * 8 + 5] = 0.f;
                      g_M[(b * HID + j) * 8 + 6] = 0.f;
                      g_M[(b * HID + j) * 8 + 7] = 0.f; }
    }
    if (tid < OUTD) {
        float c = 0.f;
#pragma unroll 8
        for (int hh = 0; hh < HID; hh++) c += btf[hh] * sh_bc[tid][hh];
        g_c[b * 8 + tid] = c;
    }
    if (tid >= OUTD && tid < 8) g_c[b * 8 + tid] = 0.f;
}

// ---------------------------------------------------------------------------
// Trunk: HMMA fp16, 2-term W-split. 256 threads, 8 warps (4M x 2N), warp
// tile 32x64. A = fp16 activations (1 plane), B = Wh + Wl.
// ---------------------------------------------------------------------------
__global__ void __launch_bounds__(256, 2)
trunk_kernel(const float* __restrict__ coords, const float* __restrict__ sdf,
             const float* __restrict__ Wt0,    const float* __restrict__ bt0,
             const float* __restrict__ bt,     const float* __restrict__ at,
             const float* __restrict__ wt,     float* __restrict__ out)
{
    extern __shared__ char smem[];
    float* sp  = (float*)(smem + SM_PAR);
    float* scr = (float*)smem;                  // fp32 scratch aliases X+W (64KB)
    const uint32_t su = (uint32_t)__cvta_generic_to_shared(smem);

    const int tid  = threadIdx.x;
    const int lane = tid & 31;
    const int wid  = tid >> 5;
    const int wm   = wid & 3;
    const int wn   = wid >> 2;
    const int la7  = lane & 7;
    const int lb3  = (lane >> 3) & 1;
    const int lb4  = lane >> 4;
    const int gid  = lane >> 2;
    const int tig  = lane & 3;
    const uint32_t swz = (uint32_t)la7 << 4;

    const int p0     = blockIdx.x * BP;
    const int bstart = p0 / NPTS;
    const int bound  = (bstart + 1) * NPTS - p0;
    const int b1     = (bstart + 1 < NB) ? bstart + 1 : NB - 1;

    // stage layer-1 half0 (32KB: Wh+Wl planes for k-rows 0..63)
    {
        const char* src = (const char*)g_WT;
#pragma unroll
        for (int i = 0; i < 8; i++)
            cp_async16(su + SM_W + (tid + i * 256) * 16, src + (tid + i * 256) * 16);
        asm volatile("cp.async.commit_group;");
    }

    if (tid < 128) sp[PAR_BT0 + tid] = bt0[tid];
    for (int i = tid; i < 512; i += 256) {
        sp[PAR_W0 + i] = Wt0[i];
        sp[PAR_AT + i] = at[i];
        sp[PAR_WT + i] = wt[i];
    }
    for (int i = tid; i < 384; i += 256) sp[PAR_BT + i] = bt[i];
    __syncthreads();

    // ---- layer 0: 2 threads per point, 64 features each ----
    {
        const int p  = tid & 127;
        const int jh = tid >> 7;
        const int gp = p0 + p;
        float c0 = coords[gp * 3 + 0];
        float c1 = coords[gp * 3 + 1];
        float c2 = coords[gp * 3 + 2];
        float c3 = sdf[gp];
        const int bpt = (p < bound) ? bstart : b1;
        const float* gv = &g_gate[(0 * NB + bpt) * HID];
#pragma unroll 4
        for (int i = 0; i < 32; i++) {
            int j = jh * 64 + 2 * i;
            float t0 = sp[PAR_BT0 + j]
                     + c0 * sp[PAR_W0 + j]       + c1 * sp[PAR_W0 + 128 + j]
                     + c2 * sp[PAR_W0 + 256 + j] + c3 * sp[PAR_W0 + 384 + j];
            float t1 = sp[PAR_BT0 + j + 1]
                     + c0 * sp[PAR_W0 + j + 1]       + c1 * sp[PAR_W0 + 128 + j + 1]
                     + c2 * sp[PAR_W0 + 256 + j + 1] + c3 * sp[PAR_W0 + 384 + j + 1];
            float x0 = rowdy_f(t0, sp[PAR_AT + j], sp[PAR_WT + j]) * __ldg(&gv[j]);
            float x1 = rowdy_f(t1, sp[PAR_AT + j + 1], sp[PAR_WT + j + 1]) * __ldg(&gv[j + 1]);
            store_x(su, p, j, x0, x1);
        }
    }

    float acc[2][8][4];

    // ---- layers 1..3 ----
    for (int l = 1; l <= 3; l++) {
        asm volatile("cp.async.wait_group 0;");
        __syncthreads();

#pragma unroll
        for (int s = 0; s < 2; s++)
#pragma unroll
            for (int t = 0; t < 8; t++)
#pragma unroll
                for (int i = 0; i < 4; i++) acc[s][t][i] = 0.f;

        for (int half = 0; half < 2; half++) {
#pragma unroll
            for (int kl = 0; kl < 4; kl++) {
                const int ks = half * 4 + kl;
                uint32_t a[2][4];
#pragma unroll
                for (int s = 0; s < 2; s++) {
                    uint32_t arow = (uint32_t)(wm * 32 + s * 16 + la7 + 8 * lb3);
                    uint32_t aoff = ((uint32_t)(ks * 32 + 16 * lb4)) ^ swz;
                    ldsm4(a[s], su + SM_X + arow * 256 + aoff);
                }
#pragma unroll
                for (int q = 0; q < 4; q++) {
                    uint32_t bh[4], bl[4];
                    uint32_t nrow = (uint32_t)(wn * 64 + q * 16 + la7 + 8 * lb4);
                    uint32_t boff = ((uint32_t)(kl * 32 + 16 * lb3)) ^ swz;
                    ldsm4(bh, su + SM_W + nrow * 128 + boff);
                    ldsm4(bl, su + SM_W + 16384 + nrow * 128 + boff);
#pragma unroll
                    for (int s = 0; s < 2; s++) {
#pragma unroll
                        for (int u = 0; u < 2; u++) {
                            float* d = acc[s][q * 2 + u];
                            mma16816(d, a[s], bh[2 * u], bh[2 * u + 1]);
                            mma16816(d, a[s], bl[2 * u], bl[2 * u + 1]);
                        }
                    }
                }
            }
            __syncthreads();
            if (half == 0) {
                const char* src = (const char*)(g_WT + ((l - 1) * 2 + 1) * 16384);
#pragma unroll
                for (int i = 0; i < 8; i++)
                    cp_async16(su + SM_W + (tid + i * 256) * 16, src + (tid + i * 256) * 16);
                asm volatile("cp.async.commit_group;");
                asm volatile("cp.async.wait_group 0;");
                __syncthreads();
            }
        }

        if (l < 3) {
            const char* src = (const char*)(g_WT + (l * 2) * 16384);
#pragma unroll
            for (int i = 0; i < 8; i++)
                cp_async16(su + SM_W + (tid + i * 256) * 16, src + (tid + i * 256) * 16);
            asm volatile("cp.async.commit_group;");
        }

        const float* bvec = &sp[PAR_BT + (l - 1) * 128];
        const float* avec = &sp[PAR_AT + l * 128];
        const float* wvec = &sp[PAR_WT + l * 128];
#pragma unroll
        for (int s = 0; s < 2; s++) {
            const int pA = wm * 32 + s * 16 + gid;
            const int bA = (pA < bound) ? bstart : b1;
            const int bB = (pA + 8 < bound) ? bstart : b1;
#pragma unroll
            for (int t = 0; t < 8; t++) {
                const int jA = wn * 64 + t * 8 + 2 * tig;
                float* d = acc[s][t];
                float x0 = rowdy_f(d[0] + bvec[jA],     avec[jA],     wvec[jA]);
                float x1 = rowdy_f(d[1] + bvec[jA + 1], avec[jA + 1], wvec[jA + 1]);
                float x2 = rowdy_f(d[2] + bvec[jA],     avec[jA],     wvec[jA]);
                float x3 = rowdy_f(d[3] + bvec[jA + 1], avec[jA + 1], wvec[jA + 1]);
                if (l < 3) {
                    const float* gA = &g_gate[(l * NB + bA) * HID];
                    const float* gB = &g_gate[(l * NB + bB) * HID];
                    x0 *= __ldg(&gA[jA]); x1 *= __ldg(&gA[jA + 1]);
                    x2 *= __ldg(&gB[jA]); x3 *= __ldg(&gB[jA + 1]);
                    store_x(su, pA,     jA, x0, x1);
                    store_x(su, pA + 8, jA, x2, x3);
                } else {
                    scr[jA * 128 + pA]           = x0;
                    scr[(jA + 1) * 128 + pA]     = x1;
                    scr[jA * 128 + pA + 8]       = x2;
                    scr[(jA + 1) * 128 + pA + 8] = x3;
                }
            }
        }
        __syncthreads();
    }

    // ---- folded final: out[p][o] = c[b][o] + sum_g x[p][g] * M'[b][g][o] ----
    {
        float* part = (float*)(smem + SM_PART);    // [5][2][128]
        const int p = tid & 127;
        const int q = tid >> 7;
        const int b = (p < bound) ? bstart : b1;
        float o0 = 0.f, o1 = 0.f, o2 = 0.f, o3 = 0.f, o4 = 0.f;
        const float4* Mb = (const float4*)&g_M[b * HID * 8];
#pragma unroll 8
        for (int g = q * 64; g < q * 64 + 64; g++) {
            float v   = scr[g * 128 + p];
            float4 m0 = __ldg(&Mb[g * 2 + 0]);
            float4 m1 = __ldg(&Mb[g * 2 + 1]);
            o0 += v * m0.x; o1 += v * m0.y; o2 += v * m0.z; o3 += v * m0.w;
            o4 += v * m1.x;
        }
        part[(0 * 2 + q) * 128 + p] = o0;
        part[(1 * 2 + q) * 128 + p] = o1;
        part[(2 * 2 + q) * 128 + p] = o2;
        part[(3 * 2 + q) * 128 + p] = o3;
        part[(4 * 2 + q) * 128 + p] = o4;
        __syncthreads();
        if (tid < BP) {
            const int gp = p0 + tid;
            const int b2 = (tid < bound) ? bstart : b1;
            float* op = out + (size_t)gp * OUTD;
#pragma unroll
            for (int o = 0; o < OUTD; o++)
                op[o] = g_c[b2 * 8 + o]
                      + part[(o * 2 + 0) * 128 + tid]
                      + part[(o * 2 + 1) * 128 + tid];
        }
    }
}

// ---------------------------------------------------------------------------
extern "C" void kernel_launch(void* const* d_in, const int* in_sizes, int n_in,
                              void* d_out, int out_size)
{
    const float* coords = (const float*)d_in[0];
    const float* sdf    = (const float*)d_in[1];
    const float* params = (const float*)d_in[2];
    const float* Wb0    = (const float*)d_in[3];
    const float* bb0    = (const float*)d_in[4];
    const float* Wb     = (const float*)d_in[5];
    const float* bb     = (const float*)d_in[6];
    const float* Wbf    = (const float*)d_in[7];
    const float* bbf    = (const float*)d_in[8];
    const float* ab     = (const float*)d_in[9];
    const float* wb     = (const float*)d_in[10];
    const float* Wt0    = (const float*)d_in[11];
    const float* bt0    = (const float*)d_in[12];
    const float* Wt     = (const float*)d_in[13];
    const float* bt     = (const float*)d_in[14];
    const float* Wtf    = (const float*)d_in[15];
    const float* btf    = (const float*)d_in[16];
    const float* at     = (const float*)d_in[17];
    const float* wt     = (const float*)d_in[18];
    float* out = (float*)d_out;

    static int smem_set = 0;
    if (!smem_set) {
        cudaFuncSetAttribute(trunk_kernel,
                             cudaFuncAttributeMaxDynamicSharedMemorySize,
                             SM_TOTAL);
        smem_set = 1;
    }

    branch_prep_kernel<<<NB + 96, 512>>>(params, Wb0, bb0, Wb, bb, Wbf, bbf,
                                         ab, wb, Wtf, btf, Wt);
    trunk_kernel<<<LTOT / BP, 256, SM_TOTAL>>>(coords, sdf, Wt0, bt0,
                                               bt, at, wt, out);
}